// round 17
// baseline (speedup 1.0000x reference)
#include <cuda_runtime.h>
#include <cuda_fp16.h>
#include <cstdint>

// GCN layer on GB300, round-17: R16 direct-bucket pipeline + half-warp
// uint4 aggregate (2 edges/step, fp16 accumulate with per-batch fp32 flush).
//   A: fill_direct -> nhs -> aggregate(+cnt reset) -> gemm12(+spill reset)
//   C: eh passthrough copy (fully parallel).

#define NN 100000
#define EE 1600000
#define DD 128
#define MTILES 6250        // 100000/16
#define CAP 64             // bucket slots per node
#define SPILLCAP 1048576
#define WSTRIDE 136
#define SMEM_GEMM (2 * DD * WSTRIDE * (int)sizeof(__half))   // 69,632B

__device__ __align__(128) int     g_cnt[NN];
__device__ __align__(128) int     g_esrc[(size_t)NN * CAP];  // 25.6MB
__device__ __align__(128) int2    g_spill[SPILLCAP];
__device__ __align__(128) __half2 g_nhs[(size_t)NN * 64];    // nh*dis fp16
__device__ __align__(128) __half2 g_xh [(size_t)NN * 64];    // agg fp16
__device__ int g_spillcnt;

// ---------- helpers ----------
__device__ __forceinline__ int edge_idx(const void* ei, int table, int e, bool is64) {
    if (is64) return (int)((const long long*)ei)[(size_t)table * EE + e];
    return ((const int*)ei)[(size_t)table * EE + e];
}
__device__ __forceinline__ uint32_t h2bits(__half2 h) {
    return *reinterpret_cast<uint32_t*>(&h);
}
__device__ __forceinline__ uint32_t packh2(float a, float b) {
    __half2 h = __floats2half2_rn(a, b);
    return *reinterpret_cast<uint32_t*>(&h);
}
__device__ __forceinline__ void mma16816(float c[4], const uint32_t a[4],
                                         uint32_t b0, uint32_t b1) {
    asm volatile(
        "mma.sync.aligned.m16n8k16.row.col.f32.f16.f16.f32 "
        "{%0,%1,%2,%3}, {%4,%5,%6,%7}, {%8,%9}, {%0,%1,%2,%3};"
        : "+f"(c[0]), "+f"(c[1]), "+f"(c[2]), "+f"(c[3])
        : "r"(a[0]), "r"(a[1]), "r"(a[2]), "r"(a[3]), "r"(b0), "r"(b1));
}
// Per-warp index-dtype detect: first 32 odd 32-bit words of edge_index.
// int64 (values < 2^31): all zero. int32: random indices, P(all 0)~1e-160.
__device__ __forceinline__ bool detect_is64(const void* ei, int lane) {
    unsigned hv = ((const unsigned*)ei)[2 * lane + 1];
    return __ballot_sync(0xffffffffu, hv != 0u) == 0u;
}

// ---------- fill_direct: histogram + bucket fill in one pass ----------
__global__ void fill_kernel(const void* __restrict__ ei) {
    const int lane = threadIdx.x & 31;
    const bool is64 = detect_is64(ei, lane);
    int e = blockIdx.x * 256 + threadIdx.x;      // EE == 6250*256 exactly
    int src = edge_idx(ei, 0, e, is64);
    int dst = edge_idx(ei, 1, e, is64);
    if ((unsigned)src >= NN || (unsigned)dst >= NN) return;
    int pos = atomicAdd(&g_cnt[dst], 1);
    if (pos < CAP) {
        g_esrc[(size_t)dst * CAP + pos] = src;
    } else {
        int sp = atomicAdd(&g_spillcnt, 1);
        if (sp < SPILLCAP) g_spill[sp] = make_int2(src, dst);
    }
}

// ---------- nhs: g_nhs[i] = fp16(nh[i] * dis[row]), dis inline ----------
__global__ void nhs_kernel(const float* __restrict__ nh) {
    int idx = blockIdx.x * blockDim.x + threadIdx.x;
    if (idx < NN * 32) {
        int row = idx >> 5;
        int c = __ldg(&g_cnt[row]);
        float d = (c > 0) ? rsqrtf((float)c) : 0.f;
        float4 v = __ldg(reinterpret_cast<const float4*>(nh) + idx);
        g_nhs[2 * idx]     = __floats2half2_rn(v.x * d, v.y * d);
        g_nhs[2 * idx + 1] = __floats2half2_rn(v.z * d, v.w * d);
    }
}

// ---------- aggregate: warp/node, half-warp uint4, fp16 accumulate --------
// Half-warp h processes edges 2j+h; lane covers 16B (8 feats) of the row.
// fp16 hadd2 accumulation, flushed to fp32 after each 32-edge batch.
// Cross-half combine via shfl_xor(16); lanes 0-15 store the uint4 row.
__global__ void aggregate_kernel() {
    int w = (blockIdx.x * blockDim.x + threadIdx.x) >> 5;
    int lane = threadIdx.x & 31;
    if (w >= NN) return;
    int len = g_cnt[w];
    int blen = min(len, CAP);
    const int* bucket = g_esrc + (size_t)w * CAP;
    const uint4* NHS4 = reinterpret_cast<const uint4*>(g_nhs);
    const int half = lane >> 4, fl = lane & 15;

    float facc[8] = {0, 0, 0, 0, 0, 0, 0, 0};
    for (int b = 0; b < blen; b += 32) {
        int n = min(32, blen - b);
        int src = (lane < n) ? __ldg(&bucket[b + lane]) : 0;
        __half2 hacc[4];
        hacc[0] = hacc[1] = hacc[2] = hacc[3] = __float2half2_rn(0.f);
        int steps = (n + 1) >> 1;
        for (int j = 0; j < steps; ++j) {
            int idx = 2 * j + half;
            int s = __shfl_sync(0xffffffffu, src, idx & 31);
            if (idx < n) {
                uint4 r = __ldg(NHS4 + (size_t)s * 16 + fl);
                hacc[0] = __hadd2(hacc[0], *reinterpret_cast<__half2*>(&r.x));
                hacc[1] = __hadd2(hacc[1], *reinterpret_cast<__half2*>(&r.y));
                hacc[2] = __hadd2(hacc[2], *reinterpret_cast<__half2*>(&r.z));
                hacc[3] = __hadd2(hacc[3], *reinterpret_cast<__half2*>(&r.w));
            }
        }
        #pragma unroll
        for (int i = 0; i < 4; ++i) {
            float2 f = __half22float2(hacc[i]);
            facc[2 * i] += f.x;
            facc[2 * i + 1] += f.y;
        }
    }

    // spill sweep (expected never; half 0 only to avoid double count)
    if (len > CAP && half == 0) {
        int sc = min(g_spillcnt, SPILLCAP);
        for (int j = 0; j < sc; ++j) {
            int2 eg = g_spill[j];
            if (eg.y == w) {
                uint4 r = __ldg(NHS4 + (size_t)eg.x * 16 + fl);
                #pragma unroll
                for (int i = 0; i < 4; ++i) {
                    float2 f = __half22float2(
                        *(reinterpret_cast<__half2*>(&r.x) + i));
                    facc[2 * i] += f.x;
                    facc[2 * i + 1] += f.y;
                }
            }
        }
    }

    // combine halves and write
    #pragma unroll
    for (int i = 0; i < 8; ++i)
        facc[i] += __shfl_xor_sync(0xffffffffu, facc[i], 16);
    if (half == 0) {
        float dd = (len > 0) ? rsqrtf((float)len) : 0.f;
        uint4 o;
        o.x = packh2(facc[0] * dd, facc[1] * dd);
        o.y = packh2(facc[2] * dd, facc[3] * dd);
        o.z = packh2(facc[4] * dd, facc[5] * dd);
        o.w = packh2(facc[6] * dd, facc[7] * dd);
        reinterpret_cast<uint4*>(g_xh)[(size_t)w * 16 + fl] = o;
    }
    if (lane == 0) g_cnt[w] = 0;        // reset for next graph replay
}

// ---------- fused GEMM1+GEMM2, register-chained HMMA (R13, best) ----------
__global__ void __launch_bounds__(256) gemm12_kernel(
    const float* __restrict__ W1, const float* __restrict__ b1,
    const float* __restrict__ W2, const float* __restrict__ b2,
    float* __restrict__ out) {
    if (blockIdx.x == 0 && threadIdx.x == 0) g_spillcnt = 0;  // replay reset
    extern __shared__ __half sW[];
    __half* sW1 = sW;
    __half* sW2 = sW + DD * WSTRIDE;
    const int tid = threadIdx.x, lane = tid & 31, warp = tid >> 5;
    const int gid = lane >> 2, tq = lane & 3;

    for (int idx = tid; idx < DD * DD; idx += 256) {
        int k = idx >> 7, n = idx & 127;
        sW1[n * WSTRIDE + k] = __float2half(W1[idx]);
        sW2[n * WSTRIDE + k] = __float2half(W2[idx]);
    }
    __syncthreads();

    for (int mt = blockIdx.x * 8 + warp; mt < MTILES; mt += gridDim.x * 8) {
        const __half2* X0 = g_xh + (size_t)(mt * 16 + gid) * 64;
        const __half2* X1 = X0 + 8 * 64;

        float acc1[16][4];
        #pragma unroll
        for (int t = 0; t < 16; ++t)
            acc1[t][0] = acc1[t][1] = acc1[t][2] = acc1[t][3] = 0.f;
        #pragma unroll
        for (int kc = 0; kc < 8; ++kc) {
            uint32_t a[4];
            a[0] = h2bits(__ldg(X0 + kc * 8 + tq));
            a[1] = h2bits(__ldg(X1 + kc * 8 + tq));
            a[2] = h2bits(__ldg(X0 + kc * 8 + 4 + tq));
            a[3] = h2bits(__ldg(X1 + kc * 8 + 4 + tq));
            #pragma unroll
            for (int t = 0; t < 16; ++t) {
                int n = 8 * t + gid;
                uint32_t b0 = h2bits(*reinterpret_cast<const __half2*>(
                    &sW1[n * WSTRIDE + kc * 16 + 2 * tq]));
                uint32_t b1v = h2bits(*reinterpret_cast<const __half2*>(
                    &sW1[n * WSTRIDE + kc * 16 + 8 + 2 * tq]));
                mma16816(acc1[t], a, b0, b1v);
            }
        }

        float acc2[16][4];
        #pragma unroll
        for (int t = 0; t < 16; ++t)
            acc2[t][0] = acc2[t][1] = acc2[t][2] = acc2[t][3] = 0.f;
        #pragma unroll
        for (int kc = 0; kc < 8; ++kc) {
            int t0 = 2 * kc, t1 = 2 * kc + 1;
            float2 bbA = __ldg(reinterpret_cast<const float2*>(b1 + 8 * t0 + 2 * tq));
            float2 bbB = __ldg(reinterpret_cast<const float2*>(b1 + 8 * t1 + 2 * tq));
            uint32_t ha[4];
            ha[0] = packh2(fmaxf(acc1[t0][0] + bbA.x, 0.f),
                           fmaxf(acc1[t0][1] + bbA.y, 0.f));
            ha[1] = packh2(fmaxf(acc1[t0][2] + bbA.x, 0.f),
                           fmaxf(acc1[t0][3] + bbA.y, 0.f));
            ha[2] = packh2(fmaxf(acc1[t1][0] + bbB.x, 0.f),
                           fmaxf(acc1[t1][1] + bbB.y, 0.f));
            ha[3] = packh2(fmaxf(acc1[t1][2] + bbB.x, 0.f),
                           fmaxf(acc1[t1][3] + bbB.y, 0.f));
            #pragma unroll
            for (int t = 0; t < 16; ++t) {
                int n = 8 * t + gid;
                uint32_t b0 = h2bits(*reinterpret_cast<const __half2*>(
                    &sW2[n * WSTRIDE + kc * 16 + 2 * tq]));
                uint32_t b1v = h2bits(*reinterpret_cast<const __half2*>(
                    &sW2[n * WSTRIDE + kc * 16 + 8 + 2 * tq]));
                mma16816(acc2[t], ha, b0, b1v);
            }
        }

        size_t r0 = (size_t)(mt * 16 + gid) * DD;
        size_t r1 = r0 + (size_t)8 * DD;
        #pragma unroll
        for (int t = 0; t < 16; ++t) {
            int n0 = 8 * t + 2 * tq;
            float2 bb = __ldg(reinterpret_cast<const float2*>(b2 + n0));
            *reinterpret_cast<float2*>(out + r0 + n0) =
                make_float2(acc2[t][0] + bb.x, acc2[t][1] + bb.y);
            *reinterpret_cast<float2*>(out + r1 + n0) =
                make_float2(acc2[t][2] + bb.x, acc2[t][3] + bb.y);
        }
    }
}

// ---------- eh passthrough (stream C) ----------
__global__ void copy_eh_kernel(const float* __restrict__ eh, float* __restrict__ out) {
    int idx = blockIdx.x * blockDim.x + threadIdx.x;
    const int total4 = EE * 16 / 4;
    if (idx < total4)
        reinterpret_cast<float4*>(out)[idx] =
            __ldg(reinterpret_cast<const float4*>(eh) + idx);
}

extern "C" void kernel_launch(void* const* d_in, const int* in_sizes, int n_in,
                              void* d_out, int out_size) {
    const float* nh = nullptr; const float* eh = nullptr; const void* ei = nullptr;
    const float* Wp[2] = {nullptr, nullptr}; const float* bp[2] = {nullptr, nullptr};
    int nw = 0, nb = 0;
    for (int i = 0; i < n_in; ++i) {
        int s = in_sizes[i];
        if (s == NN * DD)            nh = (const float*)d_in[i];
        else if (s == EE * 16)       eh = (const float*)d_in[i];
        else if (s == 2 * EE)        ei = d_in[i];
        else if (s == DD * DD) { if (nw < 2) Wp[nw++] = (const float*)d_in[i]; }
        else if (s == DD)      { if (nb < 2) bp[nb++] = (const float*)d_in[i]; }
    }
    float* out = (float*)d_out;

    // Lazy one-time setup (first call is uncaptured; reused inside capture).
    static cudaStream_t sC = nullptr;
    static cudaEvent_t evFork = nullptr, evEh = nullptr;
    static bool attrSet = false;
    if (!sC) {
        cudaStreamCreateWithFlags(&sC, cudaStreamNonBlocking);
        cudaEventCreateWithFlags(&evFork, cudaEventDisableTiming);
        cudaEventCreateWithFlags(&evEh,   cudaEventDisableTiming);
    }
    if (!attrSet) {
        cudaFuncSetAttribute(gemm12_kernel,
                             cudaFuncAttributeMaxDynamicSharedMemorySize, SMEM_GEMM);
        attrSet = true;
    }

    // ---- stream C: eh passthrough (fully independent) ----
    cudaEventRecord(evFork, 0);
    cudaStreamWaitEvent(sC, evFork, 0);
    copy_eh_kernel<<<(EE * 16 / 4 + 255) / 256, 256, 0, sC>>>(
        eh, out + (size_t)NN * DD);
    cudaEventRecord(evEh, sC);

    // ---- stream A: 4-kernel chain ----
    fill_kernel<<<EE / 256, 256>>>(ei);
    nhs_kernel<<<(NN * 32 + 255) / 256, 256>>>(nh);
    aggregate_kernel<<<(NN * 32 + 255) / 256, 256>>>();
    gemm12_kernel<<<296, 256, SMEM_GEMM>>>(Wp[0], bp[0], Wp[1], bp[1], out);

    // join stream C
    cudaStreamWaitEvent(0, evEh, 0);
}